// round 8
// baseline (speedup 1.0000x reference)
#include <cuda_runtime.h>
#include <cuda_bf16.h>
#include <cstdint>

typedef unsigned long long u64;
typedef unsigned int u32;

#define NB 16
#define NT 96
#define NN 325
#define ND 64
#define NH 64
#define NROWS (NB*NN)          // 5200
#define BTN (NB*NT*NN)         // 499200
#define HSTRIDE (NN*NH)        // 20800
#define BSTRIDE (NT*NN*NH)     // 1996800

// Fused scratch: [t][row][384] with row = b*NN+n; cols: f,i,o,u,gf,gu (64 each)
__device__ float g_AG[(size_t)BTN * 384];

// ================= helpers =================
__device__ __forceinline__ u32 smem_u32(const void* p){
    u32 a; asm("{ .reg .u64 t; cvta.to.shared.u64 t, %1; cvt.u32.u64 %0, t; }" : "=r"(a) : "l"(p));
    return a;
}
__device__ __forceinline__ u32 bfpack(float lo_elem, float hi_elem){
    u32 r; asm("cvt.rn.bf16x2.f32 %0, %1, %2;" : "=r"(r) : "f"(hi_elem), "f"(lo_elem));
    return r;
}
__device__ __forceinline__ void ldsm_x4(u32& a0,u32& a1,u32& a2,u32& a3, u32 addr){
    asm volatile("ldmatrix.sync.aligned.m8n8.x4.shared.b16 {%0,%1,%2,%3}, [%4];"
      : "=r"(a0),"=r"(a1),"=r"(a2),"=r"(a3) : "r"(addr));
}
__device__ __forceinline__ void ldsm_x2(u32& b0,u32& b1, u32 addr){
    asm volatile("ldmatrix.sync.aligned.m8n8.x2.shared.b16 {%0,%1}, [%2];"
      : "=r"(b0),"=r"(b1) : "r"(addr));
}
__device__ __forceinline__ void mma16816(float* c, const u32* a, const u32* b){
    asm volatile("mma.sync.aligned.m16n8k16.row.col.f32.bf16.bf16.f32 "
      "{%0,%1,%2,%3}, {%4,%5,%6,%7}, {%8,%9}, {%0,%1,%2,%3};"
      : "+f"(c[0]),"+f"(c[1]),"+f"(c[2]),"+f"(c[3])
      : "r"(a[0]),"r"(a[1]),"r"(a[2]),"r"(a[3]), "r"(b[0]),"r"(b[1]));
}

// =====================================================================
// Phase 1 (HMMA, proven R7): per 64-row tile fused [xUx+bx | oUg+bg]
// (N=384), split-3 bf16, register prefetch pipelining.
// =====================================================================
#define P1_THREADS 256
#define P1_ROWS 64
#define P1_TILES (BTN/P1_ROWS)   // 7800
#define P1_GRID 148

#define PITCH 400
#define S_BIAS 0
#define S_B    1536
#define S_AX   155136
#define S_AO   180736
#define P1_SMEM 206336

__global__ void __launch_bounds__(P1_THREADS, 1)
glstm_pre_mma(const float* __restrict__ x, const float* __restrict__ osrc,
              const float* __restrict__ Ux, const float* __restrict__ bx,
              const float* __restrict__ Ug, const float* __restrict__ bg)
{
    extern __shared__ unsigned char smem[];
    float* bias_s = (float*)(smem + S_BIAS);
    const int tid = threadIdx.x;
    const int w   = tid >> 5;
    const int lane = tid & 31;
    const int gid = lane >> 2, tid4 = lane & 3;

    bias_s[tid] = bx[tid];
    if (tid < 128) bias_s[256 + tid] = bg[tid];

    for (int i = tid; i < 64*256; i += P1_THREADS){
        int n = i & 255, k = i >> 8;
        float v = Ux[k*256 + n];
        __nv_bfloat16 hb = __float2bfloat16(v);
        float lo = v - __bfloat162float(hb);
        __nv_bfloat16* row = (__nv_bfloat16*)(smem + S_B + n*PITCH);
        row[k] = hb; row[128 + k] = hb;
        row[64 + k] = __float2bfloat16(lo);
    }
    for (int i = tid; i < 64*128; i += P1_THREADS){
        int n = i & 127, k = i >> 7;
        float v = Ug[k*128 + n];
        __nv_bfloat16 hb = __float2bfloat16(v);
        float lo = v - __bfloat162float(hb);
        __nv_bfloat16* row = (__nv_bfloat16*)(smem + S_B + (256 + n)*PITCH);
        row[k] = hb; row[128 + k] = hb;
        row[64 + k] = __float2bfloat16(lo);
    }

    const u32 sb = smem_u32(smem);
    u32 rowAx[4], rowAo[4];
    #pragma unroll
    for (int mi = 0; mi < 4; mi++){
        u32 off = (u32)(16*mi + (lane & 15))*PITCH + ((lane >> 4) << 4);
        rowAx[mi] = sb + S_AX + off;
        rowAo[mi] = sb + S_AO + off;
    }
    u32 rowB[6];
    #pragma unroll
    for (int ni = 0; ni < 6; ni++)
        rowB[ni] = sb + S_B + (u32)(48*w + 8*ni + (lane & 7))*PITCH + (((lane >> 3) & 1) << 4);

    const bool needx = (w <= 5), needo = (w >= 5);

    const int cr = tid >> 2, ck0 = (tid & 3) << 4;
    u32* ax32 = (u32*)(smem + S_AX + cr*PITCH);
    u32* ao32 = (u32*)(smem + S_AO + cr*PITCH);

    int tile = blockIdx.x;
    float4 xv[4], ov[4];
    {
        const float4* xp = (const float4*)(x    + (size_t)((long long)tile*P1_ROWS + cr)*64 + ck0);
        const float4* op = (const float4*)(osrc + (size_t)((long long)tile*P1_ROWS + cr)*64 + ck0);
        #pragma unroll
        for (int j = 0; j < 4; j++){ xv[j] = xp[j]; ov[j] = op[j]; }
    }

    while (tile < P1_TILES){
        const long long m0 = (long long)tile * P1_ROWS;

        #pragma unroll
        for (int j = 0; j < 4; j++){
            #pragma unroll
            for (int h = 0; h < 2; h++){
                float a = h ? xv[j].z : xv[j].x;
                float b = h ? xv[j].w : xv[j].y;
                int k = ck0 + 4*j + 2*h;
                u32 hp = bfpack(a, b);
                float ra = a - __uint_as_float(hp << 16);
                float rb = b - __uint_as_float(hp & 0xFFFF0000u);
                u32 lp = bfpack(ra, rb);
                ax32[k>>1] = hp; ax32[32 + (k>>1)] = hp; ax32[64 + (k>>1)] = lp;

                a = h ? ov[j].z : ov[j].x;
                b = h ? ov[j].w : ov[j].y;
                hp = bfpack(a, b);
                ra = a - __uint_as_float(hp << 16);
                rb = b - __uint_as_float(hp & 0xFFFF0000u);
                lp = bfpack(ra, rb);
                ao32[k>>1] = hp; ao32[32 + (k>>1)] = hp; ao32[64 + (k>>1)] = lp;
            }
        }
        __syncthreads();

        const int nxt = tile + gridDim.x;
        if (nxt < P1_TILES){
            const float4* xp = (const float4*)(x    + (size_t)((long long)nxt*P1_ROWS + cr)*64 + ck0);
            const float4* op = (const float4*)(osrc + (size_t)((long long)nxt*P1_ROWS + cr)*64 + ck0);
            #pragma unroll
            for (int j = 0; j < 4; j++){ xv[j] = xp[j]; ov[j] = op[j]; }
        }

        float acc[4][6][4];
        #pragma unroll
        for (int mi = 0; mi < 4; mi++)
            #pragma unroll
            for (int ni = 0; ni < 6; ni++)
                #pragma unroll
                for (int e = 0; e < 4; e++) acc[mi][ni][e] = 0.0f;

        #pragma unroll
        for (int kf = 0; kf < 12; kf++){
            u32 Axf[4][4], Aof[4][4];
            if (needx){
                #pragma unroll
                for (int mi = 0; mi < 4; mi++)
                    ldsm_x4(Axf[mi][0],Axf[mi][1],Axf[mi][2],Axf[mi][3], rowAx[mi] + kf*32);
            }
            if (needo){
                #pragma unroll
                for (int mi = 0; mi < 4; mi++)
                    ldsm_x4(Aof[mi][0],Aof[mi][1],Aof[mi][2],Aof[mi][3], rowAo[mi] + kf*32);
            }
            u32 Bf[6][2];
            #pragma unroll
            for (int ni = 0; ni < 6; ni++)
                ldsm_x2(Bf[ni][0], Bf[ni][1], rowB[ni] + kf*32);

            #pragma unroll
            for (int ni = 0; ni < 6; ni++){
                const bool isx = (48*w + 8*ni) < 256;
                #pragma unroll
                for (int mi = 0; mi < 4; mi++)
                    mma16816(acc[mi][ni], isx ? Axf[mi] : Aof[mi], Bf[ni]);
            }
        }
        __syncthreads();

        #pragma unroll
        for (int mi = 0; mi < 4; mi++){
            #pragma unroll
            for (int half = 0; half < 2; half++){
                int r = 16*mi + gid + 8*half;
                long long m = m0 + r;
                u32 mu = (u32)m;
                u32 qq = mu / NN;
                u32 n  = mu - qq*NN;
                u32 t  = qq % NT, b = qq / NT;
                size_t ro = (size_t)t*NROWS + (size_t)b*NN + n;
                float* pAG = g_AG + ro*384;
                #pragma unroll
                for (int ni = 0; ni < 6; ni++){
                    int col = 48*w + 8*ni + 2*tid4;
                    float2 bv = *(const float2*)&bias_s[col];
                    float2 cv;
                    cv.x = acc[mi][ni][half*2 + 0] + bv.x;
                    cv.y = acc[mi][ni][half*2 + 1] + bv.y;
                    *(float2*)(pAG + col) = cv;
                }
            }
        }
        tile = nxt;
    }
}

// =====================================================================
// Phase 2 (HMMA recurrence): 130 blocks x 40 rows (pad 48), 512 threads,
// 16 warps x 24 cols. Fused per-kf split passes (Ah*Bhi, Ah*Blo, Al*Bhi).
// apre via cp.async into gates smem; gate-store = RMW.
// =====================================================================
#define P2_THREADS 512
#define P2_R 40
#define P2_BLOCKS 130
#define HPITCH 272                  // bytes per h/B row (128 bf16 + pad)
#define GP 388                      // gates pitch (f32 words)
#define SB_B 0                      // 384*272 = 104448
#define SB_H 104448                 // 48*272  = 13056
#define SB_G 117504                 // 40*388*4 = 62080
#define P2_SMEM (117504 + 40*GP*4)  // 179584

__global__ void __launch_bounds__(P2_THREADS, 1)
glstm_rec_mma(const float* __restrict__ Vx, const float* __restrict__ Vg,
              float* __restrict__ hidden, float* __restrict__ htp, float* __restrict__ ctp)
{
    extern __shared__ unsigned char smem[];
    const u32 sb = smem_u32(smem);
    float* gates = (float*)(smem + SB_G);

    const int tid  = threadIdx.x;
    const int lane = tid & 31;
    const int w    = tid >> 5;      // 0..15
    const int gid  = lane >> 2, tid4 = lane & 3;
    const int blk  = blockIdx.x;

    // ---- build fused B = [Vx | Vg] as [n][hi(64)|lo(64)] bf16, pitch 272 ----
    for (int i = tid; i < 64*384; i += P2_THREADS){
        int k = i / 384, n = i - k*384;
        float v = (n < 256) ? Vx[k*256 + n] : Vg[k*128 + (n - 256)];
        __nv_bfloat16 hb = __float2bfloat16(v);
        __nv_bfloat16* row = (__nv_bfloat16*)(smem + SB_B + n*HPITCH);
        row[k]      = hb;
        row[64 + k] = __float2bfloat16(v - __bfloat162float(hb));
    }
    // ---- zero h (rows 0..47 incl. pad) ----
    for (int i = tid; i < 48*HPITCH/4; i += P2_THREADS)
        ((u32*)(smem + SB_H))[i] = 0;

    // ldmatrix addresses
    u32 rowA[3];
    #pragma unroll
    for (int mi = 0; mi < 3; mi++)
        rowA[mi] = sb + SB_H + (u32)(16*mi + (lane & 15))*HPITCH + ((lane >> 4) << 4);
    u32 rowB[3];
    #pragma unroll
    for (int ni = 0; ni < 3; ni++)
        rowB[ni] = sb + SB_B + (u32)(24*w + 8*ni + (lane & 7))*HPITCH + (((lane >> 3) & 1) << 4);

    // elementwise state: up to 3 element-pairs per thread (e2 = tid + 512j)
    float c0[3], c1[3];
    int gbase[3], fbase[3];
    #pragma unroll
    for (int j = 0; j < 3; j++){
        c0[j] = 0.0f; c1[j] = 0.0f;
        int e2 = tid + j*P2_THREADS;
        if (e2 < 1280){
            int r = e2 >> 5, hp = e2 & 31;
            int rho = blk*P2_R + r;
            int b = rho / NN, n = rho - b*NN;
            gbase[j] = b*BSTRIDE + n*NH + 2*hp;
            fbase[j] = rho*NH + 2*hp;
        } else { gbase[j] = 0; fbase[j] = 0; }
    }
    __syncthreads();

    for (int t = 0; t < NT; t++){
        // ---- 1) stream apre slab into gates smem (async, overlaps MMA) ----
        {
            const float* src = g_AG + ((size_t)t*NROWS + (size_t)blk*P2_R)*384;
            #pragma unroll
            for (int j = 0; j < 8; j++){
                int i = tid + j*P2_THREADS;     // 3840 chunks of 16B
                if (i < 3840){
                    int r = i / 96, c = i - r*96;
                    u32 dst = sb + SB_G + (u32)r*(GP*4) + (u32)c*16;
                    const float* s = src + (size_t)r*384 + (size_t)c*4;
                    asm volatile("cp.async.ca.shared.global [%0], [%1], 16;"
                                 :: "r"(dst), "l"(s) : "memory");
                }
            }
            asm volatile("cp.async.commit_group;" ::: "memory");
        }

        // ---- 2) MMA, acc = 0; fused split passes per kf ----
        float acc[3][3][4];
        #pragma unroll
        for (int mi = 0; mi < 3; mi++)
            #pragma unroll
            for (int ni = 0; ni < 3; ni++)
                #pragma unroll
                for (int e = 0; e < 4; e++) acc[mi][ni][e] = 0.0f;

        // loop 1: load Ah once per kf; use against B_hi then B_lo
        #pragma unroll
        for (int kf = 0; kf < 4; kf++){
            u32 Ah[3][4];
            #pragma unroll
            for (int mi = 0; mi < 3; mi++)
                ldsm_x4(Ah[mi][0],Ah[mi][1],Ah[mi][2],Ah[mi][3], rowA[mi] + kf*32);
            u32 Bh[3][2], Bl[3][2];
            #pragma unroll
            for (int ni = 0; ni < 3; ni++){
                ldsm_x2(Bh[ni][0], Bh[ni][1], rowB[ni] + kf*32);
                ldsm_x2(Bl[ni][0], Bl[ni][1], rowB[ni] + 128 + kf*32);
            }
            #pragma unroll
            for (int ni = 0; ni < 3; ni++)
                #pragma unroll
                for (int mi = 0; mi < 3; mi++){
                    mma16816(acc[mi][ni], Ah[mi], Bh[ni]);
                    mma16816(acc[mi][ni], Ah[mi], Bl[ni]);
                }
        }
        // loop 2: h_lo x W_hi
        #pragma unroll
        for (int kf = 0; kf < 4; kf++){
            u32 Al[3][4];
            #pragma unroll
            for (int mi = 0; mi < 3; mi++)
                ldsm_x4(Al[mi][0],Al[mi][1],Al[mi][2],Al[mi][3], rowA[mi] + 128 + kf*32);
            u32 Bh[3][2];
            #pragma unroll
            for (int ni = 0; ni < 3; ni++)
                ldsm_x2(Bh[ni][0], Bh[ni][1], rowB[ni] + kf*32);
            #pragma unroll
            for (int ni = 0; ni < 3; ni++)
                #pragma unroll
                for (int mi = 0; mi < 3; mi++)
                    mma16816(acc[mi][ni], Al[mi], Bh[ni]);
        }

        // ---- 3) apre landed; make visible ----
        asm volatile("cp.async.wait_group 0;" ::: "memory");
        __syncthreads();

        // ---- 4) gate-store RMW: gates = apre + acc (skip pad rows) ----
        #pragma unroll
        for (int mi = 0; mi < 3; mi++){
            #pragma unroll
            for (int half = 0; half < 2; half++){
                if (mi == 2 && half == 1) continue;
                int r = 16*mi + gid + 8*half;
                #pragma unroll
                for (int ni = 0; ni < 3; ni++){
                    int col = 24*w + 8*ni + 2*tid4;
                    float* gp = gates + (size_t)r*GP + col;
                    float2 prev = *(const float2*)gp;
                    float2 cv = make_float2(acc[mi][ni][half*2] + prev.x,
                                            acc[mi][ni][half*2 + 1] + prev.y);
                    *(float2*)gp = cv;
                }
            }
        }
        __syncthreads();   // gates complete; all h reads done

        // ---- 5) elementwise: cell update, write h (bf16 hi/lo) ----
        #pragma unroll
        for (int j = 0; j < 3; j++){
            int e2 = tid + j*P2_THREADS;
            if (e2 >= 1280) continue;
            int r = e2 >> 5, hp = e2 & 31;
            const float* g = gates + (size_t)r*GP + 2*hp;
            float2 gf_ = *(const float2*)(g + 0);
            float2 gi_ = *(const float2*)(g + 64);
            float2 go_ = *(const float2*)(g + 128);
            float2 gu_ = *(const float2*)(g + 192);
            float2 gG_ = *(const float2*)(g + 256);
            float2 gV_ = *(const float2*)(g + 320);

            float hn0, hn1;
            {
                float ef = __expf(-gf_.x);
                float eg = __expf(-gG_.x);
                float fgf = __fdividef(1.0f, 1.0f + ef + eg + ef*eg);
                float ei = __expf(-gi_.x);
                float eu = __expf(-gu_.x);
                float ev = __expf(-gV_.x);
                float iuu = __fdividef(1.0f, (1.0f+ei)*(1.0f+eu)*(1.0f+ev));
                float c = fgf*c0[j] + iuu;
                c0[j] = c;
                float ot = __fdividef(1.0f, 1.0f + __expf(-go_.x));
                float th = 1.0f - __fdividef(2.0f, 1.0f + __expf(2.0f*c));
                hn0 = ot * th;
            }
            {
                float ef = __expf(-gf_.y);
                float eg = __expf(-gG_.y);
                float fgf = __fdividef(1.0f, 1.0f + ef + eg + ef*eg);
                float ei = __expf(-gi_.y);
                float eu = __expf(-gu_.y);
                float ev = __expf(-gV_.y);
                float iuu = __fdividef(1.0f, (1.0f+ei)*(1.0f+eu)*(1.0f+ev));
                float c = fgf*c1[j] + iuu;
                c1[j] = c;
                float ot = __fdividef(1.0f, 1.0f + __expf(-go_.y));
                float th = 1.0f - __fdividef(2.0f, 1.0f + __expf(2.0f*c));
                hn1 = ot * th;
            }

            u32 hhi = bfpack(hn0, hn1);
            float r0 = hn0 - __uint_as_float(hhi << 16);
            float r1 = hn1 - __uint_as_float(hhi & 0xFFFF0000u);
            u32 hlo = bfpack(r0, r1);
            *(u32*)(smem + SB_H + r*HPITCH + 4*hp)       = hhi;
            *(u32*)(smem + SB_H + r*HPITCH + 128 + 4*hp) = hlo;

            float2 hv = make_float2(hn0, hn1);
            *(float2*)&hidden[gbase[j] + t*HSTRIDE] = hv;
            if (t == NT-1){
                *(float2*)&htp[fbase[j]] = hv;
                *(float2*)&ctp[fbase[j]] = make_float2(c0[j], c1[j]);
            }
        }
        __syncthreads();   // h(t) ready for step t+1 ldmatrix
    }
}

extern "C" void kernel_launch(void* const* d_in, const int* in_sizes, int n_in,
                              void* d_out, int out_size)
{
    const float* x   = (const float*)d_in[0];
    const float* o_s = (const float*)d_in[1];
    const float* Ux  = (const float*)d_in[2];
    const float* Vx  = (const float*)d_in[3];
    const float* bx  = (const float*)d_in[4];
    const float* Ug  = (const float*)d_in[5];
    const float* Vg  = (const float*)d_in[6];
    const float* bg  = (const float*)d_in[7];

    float* out    = (float*)d_out;
    float* hidden = out;                               // [B,T,N,H]
    float* htp    = out + (size_t)BTN * NH;            // [B,N,H]
    float* ctp    = htp + (size_t)NROWS * NH;          // [B,N,H]

    cudaFuncSetAttribute(glstm_pre_mma, cudaFuncAttributeMaxDynamicSharedMemorySize, P1_SMEM);
    cudaFuncSetAttribute(glstm_rec_mma, cudaFuncAttributeMaxDynamicSharedMemorySize, P2_SMEM);

    glstm_pre_mma<<<P1_GRID, P1_THREADS, P1_SMEM>>>(x, o_s, Ux, bx, Ug, bg);
    glstm_rec_mma<<<P2_BLOCKS, P2_THREADS, P2_SMEM>>>(Vx, Vg, hidden, htp, ctp);
}

// round 9
// speedup vs baseline: 1.0459x; 1.0459x over previous
#include <cuda_runtime.h>
#include <cuda_bf16.h>
#include <cstdint>

typedef unsigned long long u64;
typedef unsigned int u32;

#define NB 16
#define NT 96
#define NN 325
#define ND 64
#define NH 64
#define NROWS (NB*NN)          // 5200
#define BTN (NB*NT*NN)         // 499200
#define HSTRIDE (NN*NH)        // 20800
#define BSTRIDE (NT*NN*NH)     // 1996800

// Fused scratch: [t][row][384] with row = b*NN+n; cols: f,i,o,u,gf,gu (64 each)
__device__ float g_AG[(size_t)BTN * 384];

// ================= helpers =================
__device__ __forceinline__ u32 smem_u32(const void* p){
    u32 a; asm("{ .reg .u64 t; cvta.to.shared.u64 t, %1; cvt.u32.u64 %0, t; }" : "=r"(a) : "l"(p));
    return a;
}
__device__ __forceinline__ u32 bfpack(float lo_elem, float hi_elem){
    u32 r; asm("cvt.rn.bf16x2.f32 %0, %1, %2;" : "=r"(r) : "f"(hi_elem), "f"(lo_elem));
    return r;
}
__device__ __forceinline__ void ldsm_x4(u32& a0,u32& a1,u32& a2,u32& a3, u32 addr){
    asm volatile("ldmatrix.sync.aligned.m8n8.x4.shared.b16 {%0,%1,%2,%3}, [%4];"
      : "=r"(a0),"=r"(a1),"=r"(a2),"=r"(a3) : "r"(addr));
}
__device__ __forceinline__ void ldsm_x2(u32& b0,u32& b1, u32 addr){
    asm volatile("ldmatrix.sync.aligned.m8n8.x2.shared.b16 {%0,%1}, [%2];"
      : "=r"(b0),"=r"(b1) : "r"(addr));
}
__device__ __forceinline__ void mma16816(float* c, const u32* a, const u32* b){
    asm volatile("mma.sync.aligned.m16n8k16.row.col.f32.bf16.bf16.f32 "
      "{%0,%1,%2,%3}, {%4,%5,%6,%7}, {%8,%9}, {%0,%1,%2,%3};"
      : "+f"(c[0]),"+f"(c[1]),"+f"(c[2]),"+f"(c[3])
      : "r"(a[0]),"r"(a[1]),"r"(a[2]),"r"(a[3]), "r"(b[0]),"r"(b[1]));
}

// =====================================================================
// Phase 1 (HMMA, proven R7/R8): per 64-row tile fused [xUx+bx | oUg+bg]
// (N=384), split-3 bf16, register prefetch pipelining.
// =====================================================================
#define P1_THREADS 256
#define P1_ROWS 64
#define P1_TILES (BTN/P1_ROWS)   // 7800
#define P1_GRID 148

#define PITCH 400
#define S_BIAS 0
#define S_B    1536
#define S_AX   155136
#define S_AO   180736
#define P1_SMEM 206336

__global__ void __launch_bounds__(P1_THREADS, 1)
glstm_pre_mma(const float* __restrict__ x, const float* __restrict__ osrc,
              const float* __restrict__ Ux, const float* __restrict__ bx,
              const float* __restrict__ Ug, const float* __restrict__ bg)
{
    extern __shared__ unsigned char smem[];
    float* bias_s = (float*)(smem + S_BIAS);
    const int tid = threadIdx.x;
    const int w   = tid >> 5;
    const int lane = tid & 31;
    const int gid = lane >> 2, tid4 = lane & 3;

    bias_s[tid] = bx[tid];
    if (tid < 128) bias_s[256 + tid] = bg[tid];

    for (int i = tid; i < 64*256; i += P1_THREADS){
        int n = i & 255, k = i >> 8;
        float v = Ux[k*256 + n];
        __nv_bfloat16 hb = __float2bfloat16(v);
        float lo = v - __bfloat162float(hb);
        __nv_bfloat16* row = (__nv_bfloat16*)(smem + S_B + n*PITCH);
        row[k] = hb; row[128 + k] = hb;
        row[64 + k] = __float2bfloat16(lo);
    }
    for (int i = tid; i < 64*128; i += P1_THREADS){
        int n = i & 127, k = i >> 7;
        float v = Ug[k*128 + n];
        __nv_bfloat16 hb = __float2bfloat16(v);
        float lo = v - __bfloat162float(hb);
        __nv_bfloat16* row = (__nv_bfloat16*)(smem + S_B + (256 + n)*PITCH);
        row[k] = hb; row[128 + k] = hb;
        row[64 + k] = __float2bfloat16(lo);
    }

    const u32 sb = smem_u32(smem);
    u32 rowAx[4], rowAo[4];
    #pragma unroll
    for (int mi = 0; mi < 4; mi++){
        u32 off = (u32)(16*mi + (lane & 15))*PITCH + ((lane >> 4) << 4);
        rowAx[mi] = sb + S_AX + off;
        rowAo[mi] = sb + S_AO + off;
    }
    u32 rowB[6];
    #pragma unroll
    for (int ni = 0; ni < 6; ni++)
        rowB[ni] = sb + S_B + (u32)(48*w + 8*ni + (lane & 7))*PITCH + (((lane >> 3) & 1) << 4);

    const bool needx = (w <= 5), needo = (w >= 5);

    const int cr = tid >> 2, ck0 = (tid & 3) << 4;
    u32* ax32 = (u32*)(smem + S_AX + cr*PITCH);
    u32* ao32 = (u32*)(smem + S_AO + cr*PITCH);

    int tile = blockIdx.x;
    float4 xv[4], ov[4];
    {
        const float4* xp = (const float4*)(x    + (size_t)((long long)tile*P1_ROWS + cr)*64 + ck0);
        const float4* op = (const float4*)(osrc + (size_t)((long long)tile*P1_ROWS + cr)*64 + ck0);
        #pragma unroll
        for (int j = 0; j < 4; j++){ xv[j] = xp[j]; ov[j] = op[j]; }
    }

    while (tile < P1_TILES){
        const long long m0 = (long long)tile * P1_ROWS;

        #pragma unroll
        for (int j = 0; j < 4; j++){
            #pragma unroll
            for (int h = 0; h < 2; h++){
                float a = h ? xv[j].z : xv[j].x;
                float b = h ? xv[j].w : xv[j].y;
                int k = ck0 + 4*j + 2*h;
                u32 hp = bfpack(a, b);
                float ra = a - __uint_as_float(hp << 16);
                float rb = b - __uint_as_float(hp & 0xFFFF0000u);
                u32 lp = bfpack(ra, rb);
                ax32[k>>1] = hp; ax32[32 + (k>>1)] = hp; ax32[64 + (k>>1)] = lp;

                a = h ? ov[j].z : ov[j].x;
                b = h ? ov[j].w : ov[j].y;
                hp = bfpack(a, b);
                ra = a - __uint_as_float(hp << 16);
                rb = b - __uint_as_float(hp & 0xFFFF0000u);
                lp = bfpack(ra, rb);
                ao32[k>>1] = hp; ao32[32 + (k>>1)] = hp; ao32[64 + (k>>1)] = lp;
            }
        }
        __syncthreads();

        const int nxt = tile + gridDim.x;
        if (nxt < P1_TILES){
            const float4* xp = (const float4*)(x    + (size_t)((long long)nxt*P1_ROWS + cr)*64 + ck0);
            const float4* op = (const float4*)(osrc + (size_t)((long long)nxt*P1_ROWS + cr)*64 + ck0);
            #pragma unroll
            for (int j = 0; j < 4; j++){ xv[j] = xp[j]; ov[j] = op[j]; }
        }

        float acc[4][6][4];
        #pragma unroll
        for (int mi = 0; mi < 4; mi++)
            #pragma unroll
            for (int ni = 0; ni < 6; ni++)
                #pragma unroll
                for (int e = 0; e < 4; e++) acc[mi][ni][e] = 0.0f;

        #pragma unroll
        for (int kf = 0; kf < 12; kf++){
            u32 Axf[4][4], Aof[4][4];
            if (needx){
                #pragma unroll
                for (int mi = 0; mi < 4; mi++)
                    ldsm_x4(Axf[mi][0],Axf[mi][1],Axf[mi][2],Axf[mi][3], rowAx[mi] + kf*32);
            }
            if (needo){
                #pragma unroll
                for (int mi = 0; mi < 4; mi++)
                    ldsm_x4(Aof[mi][0],Aof[mi][1],Aof[mi][2],Aof[mi][3], rowAo[mi] + kf*32);
            }
            u32 Bf[6][2];
            #pragma unroll
            for (int ni = 0; ni < 6; ni++)
                ldsm_x2(Bf[ni][0], Bf[ni][1], rowB[ni] + kf*32);

            #pragma unroll
            for (int ni = 0; ni < 6; ni++){
                const bool isx = (48*w + 8*ni) < 256;
                #pragma unroll
                for (int mi = 0; mi < 4; mi++)
                    mma16816(acc[mi][ni], isx ? Axf[mi] : Aof[mi], Bf[ni]);
            }
        }
        __syncthreads();

        #pragma unroll
        for (int mi = 0; mi < 4; mi++){
            #pragma unroll
            for (int half = 0; half < 2; half++){
                int r = 16*mi + gid + 8*half;
                long long m = m0 + r;
                u32 mu = (u32)m;
                u32 qq = mu / NN;
                u32 n  = mu - qq*NN;
                u32 t  = qq % NT, b = qq / NT;
                size_t ro = (size_t)t*NROWS + (size_t)b*NN + n;
                float* pAG = g_AG + ro*384;
                #pragma unroll
                for (int ni = 0; ni < 6; ni++){
                    int col = 48*w + 8*ni + 2*tid4;
                    float2 bv = *(const float2*)&bias_s[col];
                    float2 cv;
                    cv.x = acc[mi][ni][half*2 + 0] + bv.x;
                    cv.y = acc[mi][ni][half*2 + 1] + bv.y;
                    *(float2*)(pAG + col) = cv;
                }
            }
        }
        tile = nxt;
    }
}

// =====================================================================
// Phase 2: pipelined HMMA recurrence. 130 blocks x 40 rows, split into
// halves A (24 rows, pad 32) and B (16 rows). Warps 0-7 = MMA, 8-15 =
// elementwise. Slot s: MMA(half s&1, t=s>>1) || EW(other half, prev slot).
// =====================================================================
#define P2_THREADS 512
#define P2_R 40
#define P2_BLOCKS 130
#define HPITCH 272                   // bytes per h/B row (128 bf16 + pad)
#define GP 388                       // gates pitch (f32 words)
#define SB_B  0                      // 384*272 = 104448
#define SB_HA 104448                 // 32 rows * 272 = 8704
#define SB_HB (104448 + 32*272)      // 113152; 16 rows * 272 = 4352
#define SB_GA 117504                 // 24 * GP*4 = 37248
#define SB_GB (117504 + 24*GP*4)     // 154752; 16 * GP*4 = 24832
#define P2_SMEM (154752 + 16*GP*4)   // 179584

__device__ __forceinline__ void lstm_elem(const float* g, float& c0, float& c1,
                                          float& hn0, float& hn1){
    float2 gf_ = *(const float2*)(g + 0);
    float2 gi_ = *(const float2*)(g + 64);
    float2 go_ = *(const float2*)(g + 128);
    float2 gu_ = *(const float2*)(g + 192);
    float2 gG_ = *(const float2*)(g + 256);
    float2 gV_ = *(const float2*)(g + 320);
    {
        float ef = __expf(-gf_.x);
        float eg = __expf(-gG_.x);
        float fgf = __fdividef(1.0f, 1.0f + ef + eg + ef*eg);
        float ei = __expf(-gi_.x);
        float eu = __expf(-gu_.x);
        float ev = __expf(-gV_.x);
        float iuu = __fdividef(1.0f, (1.0f+ei)*(1.0f+eu)*(1.0f+ev));
        float c = fgf*c0 + iuu;
        c0 = c;
        float ot = __fdividef(1.0f, 1.0f + __expf(-go_.x));
        float th = 1.0f - __fdividef(2.0f, 1.0f + __expf(2.0f*c));
        hn0 = ot * th;
    }
    {
        float ef = __expf(-gf_.y);
        float eg = __expf(-gG_.y);
        float fgf = __fdividef(1.0f, 1.0f + ef + eg + ef*eg);
        float ei = __expf(-gi_.y);
        float eu = __expf(-gu_.y);
        float ev = __expf(-gV_.y);
        float iuu = __fdividef(1.0f, (1.0f+ei)*(1.0f+eu)*(1.0f+ev));
        float c = fgf*c1 + iuu;
        c1 = c;
        float ot = __fdividef(1.0f, 1.0f + __expf(-go_.y));
        float th = 1.0f - __fdividef(2.0f, 1.0f + __expf(2.0f*c));
        hn1 = ot * th;
    }
}

// MMA slot: MI = #m16 tiles, NCH = cp.async chunks per thread
template<int MI, int NCH>
__device__ __forceinline__ void mma_slot(
    unsigned char* smem, u32 sb, u32 hoff, u32 goff,
    const float* apre_src, int tid, int lane, int w,
    int gid, int tid4, const u32* rowB)
{
    // 1) stream apre slab -> gates smem (overlaps MMA)
    #pragma unroll
    for (int j = 0; j < NCH; j++){
        int i = tid + j*256;
        int r = i / 96, c = i - r*96;
        u32 dst = sb + goff + (u32)r*(GP*4) + (u32)c*16;
        const float* s = apre_src + (size_t)r*384 + (size_t)c*4;
        asm volatile("cp.async.ca.shared.global [%0], [%1], 16;"
                     :: "r"(dst), "l"(s) : "memory");
    }
    asm volatile("cp.async.commit_group;" ::: "memory");

    u32 rowA[MI];
    #pragma unroll
    for (int mi = 0; mi < MI; mi++)
        rowA[mi] = sb + hoff + (u32)(16*mi + (lane & 15))*HPITCH + ((lane >> 4) << 4);

    float acc[MI][6][4];
    #pragma unroll
    for (int mi = 0; mi < MI; mi++)
        #pragma unroll
        for (int ni = 0; ni < 6; ni++)
            #pragma unroll
            for (int e = 0; e < 4; e++) acc[mi][ni][e] = 0.0f;

    // loop 1: Ah x (Bh, Bl)
    #pragma unroll
    for (int kf = 0; kf < 4; kf++){
        u32 Ah[MI][4];
        #pragma unroll
        for (int mi = 0; mi < MI; mi++)
            ldsm_x4(Ah[mi][0],Ah[mi][1],Ah[mi][2],Ah[mi][3], rowA[mi] + kf*32);
        u32 Bh[6][2], Bl[6][2];
        #pragma unroll
        for (int ni = 0; ni < 6; ni++){
            ldsm_x2(Bh[ni][0], Bh[ni][1], rowB[ni] + kf*32);
            ldsm_x2(Bl[ni][0], Bl[ni][1], rowB[ni] + 128 + kf*32);
        }
        #pragma unroll
        for (int ni = 0; ni < 6; ni++)
            #pragma unroll
            for (int mi = 0; mi < MI; mi++){
                mma16816(acc[mi][ni], Ah[mi], Bh[ni]);
                mma16816(acc[mi][ni], Ah[mi], Bl[ni]);
            }
    }
    // loop 2: Al x Bh
    #pragma unroll
    for (int kf = 0; kf < 4; kf++){
        u32 Al[MI][4];
        #pragma unroll
        for (int mi = 0; mi < MI; mi++)
            ldsm_x4(Al[mi][0],Al[mi][1],Al[mi][2],Al[mi][3], rowA[mi] + 128 + kf*32);
        u32 Bh[6][2];
        #pragma unroll
        for (int ni = 0; ni < 6; ni++)
            ldsm_x2(Bh[ni][0], Bh[ni][1], rowB[ni] + kf*32);
        #pragma unroll
        for (int ni = 0; ni < 6; ni++)
            #pragma unroll
            for (int mi = 0; mi < MI; mi++)
                mma16816(acc[mi][ni], Al[mi], Bh[ni]);
    }

    // 3) apre landed; sync MMA group so all warps' cp.async visible
    asm volatile("cp.async.wait_group 0;" ::: "memory");
    asm volatile("bar.sync 1, 256;" ::: "memory");

    // 4) gate RMW: gates = apre + acc (skip pad rows)
    float* gates = (float*)(smem + goff);
    #pragma unroll
    for (int mi = 0; mi < MI; mi++){
        #pragma unroll
        for (int hm = 0; hm < 2; hm++){
            if (MI == 2 && mi == 1 && hm == 1) continue;   // rows 24..31 pad
            int r = 16*mi + gid + 8*hm;
            #pragma unroll
            for (int ni = 0; ni < 6; ni++){
                int col = 48*w + 8*ni + 2*tid4;
                float* gp = gates + (size_t)r*GP + col;
                float2 prev = *(const float2*)gp;
                *(float2*)gp = make_float2(acc[mi][ni][2*hm]   + prev.x,
                                           acc[mi][ni][2*hm+1] + prev.y);
            }
        }
    }
}

__global__ void __launch_bounds__(P2_THREADS, 1)
glstm_rec_mma(const float* __restrict__ Vx, const float* __restrict__ Vg,
              float* __restrict__ hidden, float* __restrict__ htp, float* __restrict__ ctp)
{
    extern __shared__ unsigned char smem[];
    const u32 sb = smem_u32(smem);

    const int tid  = threadIdx.x;
    const int lane = tid & 31;
    const int w    = tid >> 5;      // 0..15
    const int gid  = lane >> 2, tid4 = lane & 3;
    const int blk  = blockIdx.x;

    // ---- build fused B = [Vx | Vg] as [n][hi(64)|lo(64)] bf16, pitch 272 ----
    for (int i = tid; i < 64*384; i += P2_THREADS){
        int k = i / 384, n = i - k*384;
        float v = (n < 256) ? Vx[k*256 + n] : Vg[k*128 + (n - 256)];
        __nv_bfloat16 hb = __float2bfloat16(v);
        __nv_bfloat16* row = (__nv_bfloat16*)(smem + SB_B + n*HPITCH);
        row[k]      = hb;
        row[64 + k] = __float2bfloat16(v - __bfloat162float(hb));
    }
    // ---- zero h (both halves, incl. pad rows) ----
    for (int i = tid; i < 48*HPITCH/4; i += P2_THREADS)
        ((u32*)(smem + SB_HA))[i] = 0;

    // MMA warps: B-weight ldmatrix addresses (each warp owns 48 cols)
    u32 rowB[6];
    if (w < 8){
        #pragma unroll
        for (int ni = 0; ni < 6; ni++)
            rowB[ni] = sb + SB_B + (u32)(48*w + 8*ni + (lane & 7))*HPITCH
                     + (((lane >> 3) & 1) << 4);
    }

    // EW warps: per-element state (half A: 3 pairs, half B: 2 pairs)
    const int ewtid = tid - 256;
    float cA0[3], cA1[3], cB0[2], cB1[2];
    int gA[3], fA[3], gB[2], fB[2];
    if (w >= 8){
        #pragma unroll
        for (int j = 0; j < 3; j++){
            cA0[j] = 0.0f; cA1[j] = 0.0f;
            int e2 = ewtid + j*256;
            int r = e2 >> 5, hp = e2 & 31;
            int rho = blk*P2_R + r;
            int b = rho / NN, n = rho - b*NN;
            gA[j] = b*BSTRIDE + n*NH + 2*hp;
            fA[j] = rho*NH + 2*hp;
        }
        #pragma unroll
        for (int j = 0; j < 2; j++){
            cB0[j] = 0.0f; cB1[j] = 0.0f;
            int e2 = ewtid + j*256;
            int r = e2 >> 5, hp = e2 & 31;
            int rho = blk*P2_R + 24 + r;
            int b = rho / NN, n = rho - b*NN;
            gB[j] = b*BSTRIDE + n*NH + 2*hp;
            fB[j] = rho*NH + 2*hp;
        }
    }
    __syncthreads();

    for (int s = 0; s < 2*NT + 1; s++){
        if (w < 8){
            if (s < 2*NT){
                const int half = s & 1, t = s >> 1;
                const float* src = g_AG
                    + ((size_t)t*NROWS + (size_t)blk*P2_R + (half ? 24 : 0))*384;
                if (half == 0)
                    mma_slot<2,9>(smem, sb, SB_HA, SB_GA, src, tid, lane, w, gid, tid4, rowB);
                else
                    mma_slot<1,6>(smem, sb, SB_HB, SB_GB, src, tid, lane, w, gid, tid4, rowB);
            }
        } else {
            if (s > 0){
                const int half = (s - 1) & 1, t = (s - 1) >> 1;
                if (half == 0){
                    float* gates = (float*)(smem + SB_GA);
                    #pragma unroll
                    for (int j = 0; j < 3; j++){
                        int e2 = ewtid + j*256;
                        int r = e2 >> 5, hp = e2 & 31;
                        float hn0, hn1;
                        lstm_elem(gates + (size_t)r*GP + 2*hp, cA0[j], cA1[j], hn0, hn1);
                        u32 hhi = bfpack(hn0, hn1);
                        float r0 = hn0 - __uint_as_float(hhi << 16);
                        float r1 = hn1 - __uint_as_float(hhi & 0xFFFF0000u);
                        u32 hlo = bfpack(r0, r1);
                        *(u32*)(smem + SB_HA + r*HPITCH + 4*hp)       = hhi;
                        *(u32*)(smem + SB_HA + r*HPITCH + 128 + 4*hp) = hlo;
                        float2 hv = make_float2(hn0, hn1);
                        *(float2*)&hidden[gA[j] + t*HSTRIDE] = hv;
                        if (t == NT-1){
                            *(float2*)&htp[fA[j]] = hv;
                            *(float2*)&ctp[fA[j]] = make_float2(cA0[j], cA1[j]);
                        }
                    }
                } else {
                    float* gates = (float*)(smem + SB_GB);
                    #pragma unroll
                    for (int j = 0; j < 2; j++){
                        int e2 = ewtid + j*256;
                        int r = e2 >> 5, hp = e2 & 31;
                        float hn0, hn1;
                        lstm_elem(gates + (size_t)r*GP + 2*hp, cB0[j], cB1[j], hn0, hn1);
                        u32 hhi = bfpack(hn0, hn1);
                        float r0 = hn0 - __uint_as_float(hhi << 16);
                        float r1 = hn1 - __uint_as_float(hhi & 0xFFFF0000u);
                        u32 hlo = bfpack(r0, r1);
                        *(u32*)(smem + SB_HB + r*HPITCH + 4*hp)       = hhi;
                        *(u32*)(smem + SB_HB + r*HPITCH + 128 + 4*hp) = hlo;
                        float2 hv = make_float2(hn0, hn1);
                        *(float2*)&hidden[gB[j] + t*HSTRIDE] = hv;
                        if (t == NT-1){
                            *(float2*)&htp[fB[j]] = hv;
                            *(float2*)&ctp[fB[j]] = make_float2(cB0[j], cB1[j]);
                        }
                    }
                }
            }
        }
        __syncthreads();   // slot boundary: gates(s) + h(s-1) published
    }
}

extern "C" void kernel_launch(void* const* d_in, const int* in_sizes, int n_in,
                              void* d_out, int out_size)
{
    const float* x   = (const float*)d_in[0];
    const float* o_s = (const float*)d_in[1];
    const float* Ux  = (const float*)d_in[2];
    const float* Vx  = (const float*)d_in[3];
    const float* bx  = (const float*)d_in[4];
    const float* Ug  = (const float*)d_in[5];
    const float* Vg  = (const float*)d_in[6];
    const float* bg  = (const float*)d_in[7];

    float* out    = (float*)d_out;
    float* hidden = out;                               // [B,T,N,H]
    float* htp    = out + (size_t)BTN * NH;            // [B,N,H]
    float* ctp    = htp + (size_t)NROWS * NH;          // [B,N,H]

    cudaFuncSetAttribute(glstm_pre_mma, cudaFuncAttributeMaxDynamicSharedMemorySize, P1_SMEM);
    cudaFuncSetAttribute(glstm_rec_mma, cudaFuncAttributeMaxDynamicSharedMemorySize, P2_SMEM);

    glstm_pre_mma<<<P1_GRID, P1_THREADS, P1_SMEM>>>(x, o_s, Ux, bx, Ug, bg);
    glstm_rec_mma<<<P2_BLOCKS, P2_THREADS, P2_SMEM>>>(Vx, Vg, hidden, htp, ctp);
}